// round 1
// baseline (speedup 1.0000x reference)
#include <cuda_runtime.h>
#include <math.h>

#define HID   768
#define NH    12
#define DH    64
#define BATCH 4
#define SEQ   2048
#define MTOT  (BATCH*SEQ)   // 8192

// Scratch (allocation-free rule: __device__ globals)
__device__ float g_q[MTOT*HID];
__device__ float g_k[MTOT*HID];
__device__ float g_v[MTOT*HID];
__device__ float g_ctx[MTOT*HID];

// ---------------------------------------------------------------------------
// GEMM: C[M,N] = A[M,K] @ W[K,N] + bias, optional exact GELU
// 64x64 tile, BK=16, 256 threads (16x16), 4x4 microtile per thread.
// ---------------------------------------------------------------------------
template<bool GELU>
__global__ __launch_bounds__(256) void gemm_kernel(
    const float* __restrict__ A, const float* __restrict__ W,
    const float* __restrict__ bias, float* __restrict__ C,
    int M, int K, int N)
{
    __shared__ __align__(16) float As[16][65];  // [kk][m], padded
    __shared__ __align__(16) float Bs[16][64];  // [kk][n]

    const int tid = threadIdx.x;
    const int tx  = tid & 15;
    const int ty  = tid >> 4;
    const int m0  = blockIdx.y * 64;
    const int n0  = blockIdx.x * 64;

    float acc[4][4] = {};

    for (int k0 = 0; k0 < K; k0 += 16) {
        #pragma unroll
        for (int i = tid; i < 64*16; i += 256) {
            int m  = i >> 4;
            int kk = i & 15;
            As[kk][m] = A[(size_t)(m0 + m) * K + k0 + kk];
        }
        #pragma unroll
        for (int i = tid; i < 16*64; i += 256) {
            int kk = i >> 6;
            int n  = i & 63;
            Bs[kk][n] = W[(size_t)(k0 + kk) * N + n0 + n];
        }
        __syncthreads();

        #pragma unroll
        for (int kk = 0; kk < 16; kk++) {
            float a[4];
            #pragma unroll
            for (int i = 0; i < 4; i++) a[i] = As[kk][4*ty + i];
            float4 bb = *(const float4*)&Bs[kk][4*tx];
            float b[4] = {bb.x, bb.y, bb.z, bb.w};
            #pragma unroll
            for (int i = 0; i < 4; i++)
                #pragma unroll
                for (int j = 0; j < 4; j++)
                    acc[i][j] += a[i] * b[j];
        }
        __syncthreads();
    }

    #pragma unroll
    for (int i = 0; i < 4; i++) {
        int m = m0 + 4*ty + i;
        #pragma unroll
        for (int j = 0; j < 4; j++) {
            int n = n0 + 4*tx + j;
            float val = acc[i][j] + bias[n];
            if (GELU) val = val * normcdff(val);   // exact erf-based GELU
            C[(size_t)m * N + n] = val;
        }
    }
}

// ---------------------------------------------------------------------------
// Flash attention: one block per (b, h, 64-query tile). 256 threads.
// TQ=TK=64, D=64. Online softmax; mask applied as ext*s - (1-ext)*1e9.
// Dynamic smem: Qs/Ks/Vs/Ps each [64][65] floats = 66560 bytes.
// ---------------------------------------------------------------------------
__global__ __launch_bounds__(256) void attn_kernel(
    const float* __restrict__ q, const float* __restrict__ kmat,
    const float* __restrict__ vmat, const float* __restrict__ mask,
    float* __restrict__ ctx)
{
    extern __shared__ float sm[];
    float (*Qs)[65] = (float(*)[65])(sm);
    float (*Ks)[65] = (float(*)[65])(sm + 64*65);
    float (*Vs)[65] = (float(*)[65])(sm + 2*64*65);
    float (*Ps)[65] = (float(*)[65])(sm + 3*64*65);

    const int tid = threadIdx.x;
    const int tx  = tid & 15;
    const int ty  = tid >> 4;
    const int b   = blockIdx.z;
    const int h   = blockIdx.y;
    const int q0  = blockIdx.x * 64;
    const int bS  = b * SEQ;
    const float scale = 0.125f;  // 1/sqrt(64)

    // Load Q tile
    #pragma unroll
    for (int i = tid; i < 64*64; i += 256) {
        int r = i >> 6, c = i & 63;
        Qs[r][c] = q[(size_t)(bS + q0 + r) * HID + h*DH + c];
    }
    float mq[4];
    #pragma unroll
    for (int i = 0; i < 4; i++) mq[i] = mask[bS + q0 + 4*ty + i];

    float mrow[4], lrow[4], acc[4][4] = {};
    #pragma unroll
    for (int i = 0; i < 4; i++) { mrow[i] = -1e30f; lrow[i] = 0.0f; }

    for (int kt = 0; kt < SEQ/64; kt++) {
        const int k0 = kt * 64;
        // Load K, V tiles
        #pragma unroll
        for (int i = tid; i < 64*64; i += 256) {
            int r = i >> 6, c = i & 63;
            Ks[r][c] = kmat[(size_t)(bS + k0 + r) * HID + h*DH + c];
            Vs[r][c] = vmat[(size_t)(bS + k0 + r) * HID + h*DH + c];
        }
        __syncthreads();  // covers Qs on first iter too

        float mk[4];
        #pragma unroll
        for (int j = 0; j < 4; j++) mk[j] = mask[bS + k0 + 4*tx + j];

        // scores: s[i][j] = Q[4ty+i] . K[4tx+j]
        float s[4][4] = {};
        #pragma unroll 8
        for (int kk = 0; kk < 64; kk++) {
            float qv[4], kv[4];
            #pragma unroll
            for (int i = 0; i < 4; i++) qv[i] = Qs[4*ty + i][kk];
            #pragma unroll
            for (int j = 0; j < 4; j++) kv[j] = Ks[4*tx + j][kk];
            #pragma unroll
            for (int i = 0; i < 4; i++)
                #pragma unroll
                for (int j = 0; j < 4; j++)
                    s[i][j] += qv[i] * kv[j];
        }

        // scale + mask
        #pragma unroll
        for (int i = 0; i < 4; i++)
            #pragma unroll
            for (int j = 0; j < 4; j++) {
                float ext = mq[i] * mk[j];
                s[i][j] = ext * (s[i][j] * scale) - (1.0f - ext) * 1e9f;
            }

        // online softmax update (row = 16 tx lanes; xor 1,2,4,8 stays in group)
        #pragma unroll
        for (int i = 0; i < 4; i++) {
            float tm = fmaxf(fmaxf(s[i][0], s[i][1]), fmaxf(s[i][2], s[i][3]));
            #pragma unroll
            for (int off = 8; off >= 1; off >>= 1)
                tm = fmaxf(tm, __shfl_xor_sync(0xffffffffu, tm, off));
            float mnew  = fmaxf(mrow[i], tm);
            float alpha = __expf(mrow[i] - mnew);
            float rs = 0.0f;
            #pragma unroll
            for (int j = 0; j < 4; j++) {
                s[i][j] = __expf(s[i][j] - mnew);
                rs += s[i][j];
            }
            #pragma unroll
            for (int off = 8; off >= 1; off >>= 1)
                rs += __shfl_xor_sync(0xffffffffu, rs, off);
            lrow[i] = lrow[i] * alpha + rs;
            #pragma unroll
            for (int j = 0; j < 4; j++) acc[i][j] *= alpha;
            mrow[i] = mnew;
        }

        // stage P
        #pragma unroll
        for (int i = 0; i < 4; i++)
            #pragma unroll
            for (int j = 0; j < 4; j++)
                Ps[4*ty + i][4*tx + j] = s[i][j];
        __syncthreads();

        // acc += P @ V  (O columns d = 4tx..4tx+3)
        #pragma unroll 8
        for (int kk = 0; kk < 64; kk++) {
            float pv[4], vv[4];
            #pragma unroll
            for (int i = 0; i < 4; i++) pv[i] = Ps[4*ty + i][kk];
            #pragma unroll
            for (int j = 0; j < 4; j++) vv[j] = Vs[kk][4*tx + j];
            #pragma unroll
            for (int i = 0; i < 4; i++)
                #pragma unroll
                for (int j = 0; j < 4; j++)
                    acc[i][j] += pv[i] * vv[j];
        }
        __syncthreads();  // before next tile overwrites Ks/Vs/Ps
    }

    #pragma unroll
    for (int i = 0; i < 4; i++) {
        float inv = 1.0f / lrow[i];
        #pragma unroll
        for (int j = 0; j < 4; j++)
            ctx[(size_t)(bS + q0 + 4*ty + i) * HID + h*DH + 4*tx + j] = acc[i][j] * inv;
    }
}

// ---------------------------------------------------------------------------
extern "C" void kernel_launch(void* const* d_in, const int* in_sizes, int n_in,
                              void* d_out, int out_size)
{
    const float* hs   = (const float*)d_in[0];
    const float* mask = (const float*)d_in[1];
    const float* Wq   = (const float*)d_in[2];
    const float* bq   = (const float*)d_in[3];
    const float* Wk   = (const float*)d_in[4];
    const float* bk   = (const float*)d_in[5];
    const float* Wv   = (const float*)d_in[6];
    const float* bv   = (const float*)d_in[7];
    const float* Wo   = (const float*)d_in[8];
    const float* bo   = (const float*)d_in[9];
    float* out = (float*)d_out;

    float *qb, *kb, *vb, *cb;
    cudaGetSymbolAddress((void**)&qb, g_q);
    cudaGetSymbolAddress((void**)&kb, g_k);
    cudaGetSymbolAddress((void**)&vb, g_v);
    cudaGetSymbolAddress((void**)&cb, g_ctx);

    dim3 ggrid(HID/64, MTOT/64);   // (12, 128)
    gemm_kernel<false><<<ggrid, 256>>>(hs, Wq, bq, qb, MTOT, HID, HID);
    gemm_kernel<false><<<ggrid, 256>>>(hs, Wk, bk, kb, MTOT, HID, HID);
    gemm_kernel<false><<<ggrid, 256>>>(hs, Wv, bv, vb, MTOT, HID, HID);

    const int smem = 4 * 64 * 65 * sizeof(float);  // 66560
    cudaFuncSetAttribute(attn_kernel, cudaFuncAttributeMaxDynamicSharedMemorySize, smem);
    dim3 agrid(SEQ/64, NH, BATCH);                 // (32, 12, 4)
    attn_kernel<<<agrid, 256, smem>>>(qb, kb, vb, mask, cb);

    gemm_kernel<true><<<ggrid, 256>>>(cb, Wo, bo, out, MTOT, HID, HID);
}

// round 2
// speedup vs baseline: 2.8793x; 2.8793x over previous
#include <cuda_runtime.h>
#include <math.h>
#include <stdint.h>

#define HID   768
#define NH    12
#define DH    64
#define BATCH 4
#define SEQ   2048
#define MTOT  (BATCH*SEQ)   // 8192

// Scratch (allocation-free rule: __device__ globals)
__device__ float g_q[MTOT*HID];
__device__ float g_k[MTOT*HID];
__device__ float g_v[MTOT*HID];
__device__ float g_ctx[MTOT*HID];

// ---------------------------------------------------------------------------
__device__ __forceinline__ uint32_t f2tf(float x) {
    uint32_t r;
    asm("cvt.rna.tf32.f32 %0, %1;" : "=r"(r) : "f"(x));
    return r;
}

__device__ __forceinline__ void mma_tf32(float c[4],
    uint32_t a0, uint32_t a1, uint32_t a2, uint32_t a3,
    uint32_t b0, uint32_t b1)
{
    asm volatile(
        "mma.sync.aligned.m16n8k8.row.col.f32.tf32.tf32.f32 "
        "{%0,%1,%2,%3}, {%4,%5,%6,%7}, {%8,%9}, {%0,%1,%2,%3};"
        : "+f"(c[0]), "+f"(c[1]), "+f"(c[2]), "+f"(c[3])
        : "r"(a0), "r"(a1), "r"(a2), "r"(a3), "r"(b0), "r"(b1));
}

// ---------------------------------------------------------------------------
// GEMM: C[M,N] = A[M,K] @ W[K,N] + bias (+ exact GELU)
// BM=128, BN=64, BK=16. 256 threads = 8 warps in 4x2; warp tile 32x32.
// ---------------------------------------------------------------------------
template<bool GELU>
__global__ __launch_bounds__(256) void gemm_tf32(
    const float* __restrict__ A, const float* __restrict__ W,
    const float* __restrict__ bias, float* __restrict__ C,
    int M, int K, int N)
{
    __shared__ uint32_t As[128][20];  // [m][k], pad 20 -> conflict-free frag reads
    __shared__ uint32_t Bs[16][72];   // [k][n], pad 72 -> conflict-free frag reads

    const int tid  = threadIdx.x;
    const int lane = tid & 31;
    const int warp = tid >> 5;
    const int wm   = (warp >> 1) * 32;
    const int wn   = (warp & 1) * 32;
    const int m0   = blockIdx.y * 128;
    const int n0   = blockIdx.x * 64;

    float acc[2][4][4] = {};

    for (int k0 = 0; k0 < K; k0 += 16) {
        // A tile 128x16: 2 float4 per thread
        {
            int r = tid >> 2, c = (tid & 3) * 4;
            #pragma unroll
            for (int p = 0; p < 2; p++) {
                int row = r + p * 64;
                float4 v = *(const float4*)&A[(size_t)(m0 + row) * K + k0 + c];
                uint4 t = make_uint4(f2tf(v.x), f2tf(v.y), f2tf(v.z), f2tf(v.w));
                *(uint4*)&As[row][c] = t;
            }
        }
        // B tile 16x64: 1 float4 per thread
        {
            int kk = tid >> 4, c = (tid & 15) * 4;
            float4 v = *(const float4*)&W[(size_t)(k0 + kk) * N + n0 + c];
            uint4 t = make_uint4(f2tf(v.x), f2tf(v.y), f2tf(v.z), f2tf(v.w));
            *(uint4*)&Bs[kk][c] = t;
        }
        __syncthreads();

        #pragma unroll
        for (int ks = 0; ks < 16; ks += 8) {
            uint32_t a[2][4];
            #pragma unroll
            for (int mt = 0; mt < 2; mt++) {
                int r = wm + mt * 16 + (lane >> 2);
                a[mt][0] = As[r    ][ks + (lane & 3)];
                a[mt][1] = As[r + 8][ks + (lane & 3)];
                a[mt][2] = As[r    ][ks + (lane & 3) + 4];
                a[mt][3] = As[r + 8][ks + (lane & 3) + 4];
            }
            #pragma unroll
            for (int nt = 0; nt < 4; nt++) {
                uint32_t b0 = Bs[ks + (lane & 3)    ][wn + nt * 8 + (lane >> 2)];
                uint32_t b1 = Bs[ks + (lane & 3) + 4][wn + nt * 8 + (lane >> 2)];
                mma_tf32(acc[0][nt], a[0][0], a[0][1], a[0][2], a[0][3], b0, b1);
                mma_tf32(acc[1][nt], a[1][0], a[1][1], a[1][2], a[1][3], b0, b1);
            }
        }
        __syncthreads();
    }

    #pragma unroll
    for (int mt = 0; mt < 2; mt++) {
        int r0 = m0 + wm + mt * 16 + (lane >> 2);
        #pragma unroll
        for (int nt = 0; nt < 4; nt++) {
            int col = n0 + wn + nt * 8 + 2 * (lane & 3);
            float bv0 = bias[col], bv1 = bias[col + 1];
            float v0 = acc[mt][nt][0] + bv0;
            float v1 = acc[mt][nt][1] + bv1;
            float v2 = acc[mt][nt][2] + bv0;
            float v3 = acc[mt][nt][3] + bv1;
            if (GELU) {
                v0 *= normcdff(v0); v1 *= normcdff(v1);
                v2 *= normcdff(v2); v3 *= normcdff(v3);
            }
            *(float2*)&C[(size_t)r0       * N + col] = make_float2(v0, v1);
            *(float2*)&C[(size_t)(r0 + 8) * N + col] = make_float2(v2, v3);
        }
    }
}

// ---------------------------------------------------------------------------
// Flash attention, tf32 mma. Block = (b, h, 64-q-tile), 128 threads (4 warps).
// Warp w owns q rows [w*16, w*16+16). K/V tiles of 64 streamed through smem.
// ---------------------------------------------------------------------------
__global__ __launch_bounds__(128) void attn_tf32(
    const float* __restrict__ qg, const float* __restrict__ kg,
    const float* __restrict__ vg, const float* __restrict__ mask,
    float* __restrict__ ctx)
{
    extern __shared__ uint32_t smu[];
    uint32_t (*Qs)[68] = (uint32_t(*)[68])(smu);
    uint32_t (*Ks)[68] = (uint32_t(*)[68])(smu + 64 * 68);
    uint32_t (*Ps)[68] = (uint32_t(*)[68])(smu + 2 * 64 * 68);
    uint32_t (*Vs)[72] = (uint32_t(*)[72])(smu + 3 * 64 * 68);
    float* ms          = (float*)(smu + 3 * 64 * 68 + 64 * 72);

    const int tid  = threadIdx.x;
    const int lane = tid & 31;
    const int warp = tid >> 5;
    const int b    = blockIdx.z;
    const int h    = blockIdx.y;
    const int q0   = blockIdx.x * 64;
    const int bS   = b * SEQ;
    const float scale = 0.125f;   // 1/sqrt(64)

    // Load Q tile (64x64), tf32-convert into smem
    #pragma unroll
    for (int p = 0; p < 8; p++) {
        int r = p * 8 + (tid >> 4);
        int c = (tid & 15) * 4;
        float4 v = *(const float4*)&qg[(size_t)(bS + q0 + r) * HID + h * DH + c];
        *(uint4*)&Qs[r][c] = make_uint4(f2tf(v.x), f2tf(v.y), f2tf(v.z), f2tf(v.w));
    }

    const float mq0 = mask[bS + q0 + warp * 16 + (lane >> 2)];
    const float mq1 = mask[bS + q0 + warp * 16 + (lane >> 2) + 8];

    float mrow0 = -1e30f, mrow1 = -1e30f, l0 = 0.0f, l1 = 0.0f;
    float o[8][4] = {};

    for (int kt = 0; kt < SEQ / 64; kt++) {
        const int k0 = kt * 64;
        // Load K, V tiles
        #pragma unroll
        for (int p = 0; p < 8; p++) {
            int r = p * 8 + (tid >> 4);
            int c = (tid & 15) * 4;
            size_t off = (size_t)(bS + k0 + r) * HID + h * DH + c;
            float4 kv = *(const float4*)&kg[off];
            float4 vv = *(const float4*)&vg[off];
            *(uint4*)&Ks[r][c] = make_uint4(f2tf(kv.x), f2tf(kv.y), f2tf(kv.z), f2tf(kv.w));
            *(uint4*)&Vs[r][c] = make_uint4(f2tf(vv.x), f2tf(vv.y), f2tf(vv.z), f2tf(vv.w));
        }
        if (tid < 64) ms[tid] = mask[bS + k0 + tid];
        __syncthreads();

        // scores S = Q K^T  (per warp: 16 x 64)
        float s[8][4] = {};
        #pragma unroll
        for (int ks = 0; ks < 64; ks += 8) {
            int r = warp * 16 + (lane >> 2);
            uint32_t a0 = Qs[r    ][ks + (lane & 3)];
            uint32_t a1 = Qs[r + 8][ks + (lane & 3)];
            uint32_t a2 = Qs[r    ][ks + (lane & 3) + 4];
            uint32_t a3 = Qs[r + 8][ks + (lane & 3) + 4];
            #pragma unroll
            for (int nt = 0; nt < 8; nt++) {
                uint32_t b0 = Ks[nt * 8 + (lane >> 2)][ks + (lane & 3)];
                uint32_t b1 = Ks[nt * 8 + (lane >> 2)][ks + (lane & 3) + 4];
                mma_tf32(s[nt], a0, a1, a2, a3, b0, b1);
            }
        }

        // scale + mask (ext*s - (1-ext)*1e9)
        #pragma unroll
        for (int nt = 0; nt < 8; nt++) {
            float mk0 = ms[nt * 8 + 2 * (lane & 3)];
            float mk1 = ms[nt * 8 + 2 * (lane & 3) + 1];
            float e;
            e = mq0 * mk0; s[nt][0] = e * (s[nt][0] * scale) - (1.0f - e) * 1e9f;
            e = mq0 * mk1; s[nt][1] = e * (s[nt][1] * scale) - (1.0f - e) * 1e9f;
            e = mq1 * mk0; s[nt][2] = e * (s[nt][2] * scale) - (1.0f - e) * 1e9f;
            e = mq1 * mk1; s[nt][3] = e * (s[nt][3] * scale) - (1.0f - e) * 1e9f;
        }

        // online softmax (rows live in 4-lane groups -> xor 1,2)
        float tm0 = -1e30f, tm1 = -1e30f;
        #pragma unroll
        for (int nt = 0; nt < 8; nt++) {
            tm0 = fmaxf(tm0, fmaxf(s[nt][0], s[nt][1]));
            tm1 = fmaxf(tm1, fmaxf(s[nt][2], s[nt][3]));
        }
        tm0 = fmaxf(tm0, __shfl_xor_sync(0xffffffffu, tm0, 1));
        tm0 = fmaxf(tm0, __shfl_xor_sync(0xffffffffu, tm0, 2));
        tm1 = fmaxf(tm1, __shfl_xor_sync(0xffffffffu, tm1, 1));
        tm1 = fmaxf(tm1, __shfl_xor_sync(0xffffffffu, tm1, 2));

        float mn0 = fmaxf(mrow0, tm0), mn1 = fmaxf(mrow1, tm1);
        float al0 = __expf(mrow0 - mn0), al1 = __expf(mrow1 - mn1);
        float rs0 = 0.0f, rs1 = 0.0f;
        #pragma unroll
        for (int nt = 0; nt < 8; nt++) {
            s[nt][0] = __expf(s[nt][0] - mn0); rs0 += s[nt][0];
            s[nt][1] = __expf(s[nt][1] - mn0); rs0 += s[nt][1];
            s[nt][2] = __expf(s[nt][2] - mn1); rs1 += s[nt][2];
            s[nt][3] = __expf(s[nt][3] - mn1); rs1 += s[nt][3];
        }
        rs0 += __shfl_xor_sync(0xffffffffu, rs0, 1);
        rs0 += __shfl_xor_sync(0xffffffffu, rs0, 2);
        rs1 += __shfl_xor_sync(0xffffffffu, rs1, 1);
        rs1 += __shfl_xor_sync(0xffffffffu, rs1, 2);

        l0 = l0 * al0 + rs0;  l1 = l1 * al1 + rs1;
        mrow0 = mn0;  mrow1 = mn1;
        #pragma unroll
        for (int nt = 0; nt < 8; nt++) {
            o[nt][0] *= al0; o[nt][1] *= al0;
            o[nt][2] *= al1; o[nt][3] *= al1;
        }

        // P -> smem (warp-private rows)
        {
            int pr = warp * 16 + (lane >> 2);
            #pragma unroll
            for (int nt = 0; nt < 8; nt++) {
                int pc = nt * 8 + 2 * (lane & 3);
                Ps[pr    ][pc]     = f2tf(s[nt][0]);
                Ps[pr    ][pc + 1] = f2tf(s[nt][1]);
                Ps[pr + 8][pc]     = f2tf(s[nt][2]);
                Ps[pr + 8][pc + 1] = f2tf(s[nt][3]);
            }
        }
        __syncwarp();

        // O += P V  (per warp: 16 x 64)
        #pragma unroll
        for (int ks = 0; ks < 64; ks += 8) {
            int r = warp * 16 + (lane >> 2);
            uint32_t a0 = Ps[r    ][ks + (lane & 3)];
            uint32_t a1 = Ps[r + 8][ks + (lane & 3)];
            uint32_t a2 = Ps[r    ][ks + (lane & 3) + 4];
            uint32_t a3 = Ps[r + 8][ks + (lane & 3) + 4];
            #pragma unroll
            for (int nt = 0; nt < 8; nt++) {
                uint32_t b0 = Vs[ks + (lane & 3)    ][nt * 8 + (lane >> 2)];
                uint32_t b1 = Vs[ks + (lane & 3) + 4][nt * 8 + (lane >> 2)];
                mma_tf32(o[nt], a0, a1, a2, a3, b0, b1);
            }
        }
        __syncthreads();   // protect Ks/Vs/ms (and prev-iter Ps) before reload
    }

    // epilogue: divide by l, write ctx
    float inv0 = 1.0f / l0, inv1 = 1.0f / l1;
    int gr = bS + q0 + warp * 16 + (lane >> 2);
    #pragma unroll
    for (int nt = 0; nt < 8; nt++) {
        int col = h * DH + nt * 8 + 2 * (lane & 3);
        *(float2*)&ctx[(size_t)gr       * HID + col] = make_float2(o[nt][0] * inv0, o[nt][1] * inv0);
        *(float2*)&ctx[(size_t)(gr + 8) * HID + col] = make_float2(o[nt][2] * inv1, o[nt][3] * inv1);
    }
}

// ---------------------------------------------------------------------------
extern "C" void kernel_launch(void* const* d_in, const int* in_sizes, int n_in,
                              void* d_out, int out_size)
{
    const float* hs   = (const float*)d_in[0];
    const float* mask = (const float*)d_in[1];
    const float* Wq   = (const float*)d_in[2];
    const float* bq   = (const float*)d_in[3];
    const float* Wk   = (const float*)d_in[4];
    const float* bk   = (const float*)d_in[5];
    const float* Wv   = (const float*)d_in[6];
    const float* bv   = (const float*)d_in[7];
    const float* Wo   = (const float*)d_in[8];
    const float* bo   = (const float*)d_in[9];
    float* out = (float*)d_out;

    float *qb, *kb, *vb, *cb;
    cudaGetSymbolAddress((void**)&qb, g_q);
    cudaGetSymbolAddress((void**)&kb, g_k);
    cudaGetSymbolAddress((void**)&vb, g_v);
    cudaGetSymbolAddress((void**)&cb, g_ctx);

    dim3 ggrid(HID / 64, MTOT / 128);   // (12, 64)
    gemm_tf32<false><<<ggrid, 256>>>(hs, Wq, bq, qb, MTOT, HID, HID);
    gemm_tf32<false><<<ggrid, 256>>>(hs, Wk, bk, kb, MTOT, HID, HID);
    gemm_tf32<false><<<ggrid, 256>>>(hs, Wv, bv, vb, MTOT, HID, HID);

    const int smem = (3 * 64 * 68 + 64 * 72) * 4 + 64 * 4;   // 70912 B
    cudaFuncSetAttribute(attn_tf32, cudaFuncAttributeMaxDynamicSharedMemorySize, smem);
    dim3 agrid(SEQ / 64, NH, BATCH);    // (32, 12, 4)
    attn_tf32<<<agrid, 128, smem>>>(qb, kb, vb, mask, cb);

    gemm_tf32<true><<<ggrid, 256>>>(cb, Wo, bo, out, MTOT, HID, HID);
}